// round 5
// baseline (speedup 1.0000x reference)
#include <cuda_runtime.h>

// Shapes (fixed):
//   image: (3, 512, 512) f32
//   x:     (16, 1, 512, 512) f32
//   W:     (9, 3, 3, 3) f32   b: (9,) f32
//   out:   (16, 1, 512, 512) f32
//
// K[c,i,j] = b[c] + sum_{m,u,v} W[c,m,u,v] * image[m, i+u-1, j+v-1]  (zero pad)
// y[n,i,j] = sum_{u,v} x[n, i+u-1, j+v-1] * K[u*3+v, i, j]           (zero pad)
//
// Packed-pair scheme: each thread owns 4 pixels; pixel pairs (0,1) and (2,3)
// ride in 64-bit registers processed by fma.rn.f32x2 (1 instr = 2 fp32 FMAs).

#define HH 512
#define WW 512
#define NB 16
#define PLANE (HH * WW)

typedef unsigned long long u64;

__device__ __forceinline__ u64 pk2(float lo, float hi) {
    u64 r;
    asm("mov.b64 %0, {%1, %2};" : "=l"(r)
        : "r"(__float_as_uint(lo)), "r"(__float_as_uint(hi)));
    return r;
}
__device__ __forceinline__ void upk2(u64 v, float& lo, float& hi) {
    unsigned a, b;
    asm("mov.b64 {%0, %1}, %2;" : "=r"(a), "=r"(b) : "l"(v));
    lo = __uint_as_float(a);
    hi = __uint_as_float(b);
}
__device__ __forceinline__ u64 ffma2(u64 a, u64 b, u64 c) {
    u64 d;
    asm("fma.rn.f32x2 %0, %1, %2, %3;" : "=l"(d) : "l"(a), "l"(b), "l"(c));
    return d;
}

// Load a 6-wide row window [col0-1 .. col0+4] with zero padding (raw floats).
__device__ __forceinline__ void load_row6(const float* __restrict__ base,
                                          bool rowok, bool leftok, bool rightok,
                                          float r[6])
{
    if (rowok) {
        float4 v = *(const float4*)base;          // cols col0..col0+3 (16B aligned)
        r[1] = v.x; r[2] = v.y; r[3] = v.z; r[4] = v.w;
        r[0] = leftok  ? base[-1] : 0.0f;
        r[5] = rightok ? base[4]  : 0.0f;
    } else {
        r[0] = r[1] = r[2] = r[3] = r[4] = r[5] = 0.0f;
    }
}

__device__ __forceinline__ void load_win3(const float* __restrict__ cbase,
                                          bool rok0, bool rok2,
                                          bool lok, bool rtok,
                                          float r[3][6])
{
    load_row6(cbase - WW, rok0, lok, rtok, r[0]);
    load_row6(cbase,      true, lok, rtok, r[1]);
    load_row6(cbase + WW, rok2, lok, rtok, r[2]);
}

// P[k] = (r[k], r[k+1]) for k = 0..4
__device__ __forceinline__ void make_pairs(const float r[6], u64 P[5]) {
    P[0] = pk2(r[0], r[1]);
    P[1] = pk2(r[1], r[2]);
    P[2] = pk2(r[2], r[3]);
    P[3] = pk2(r[3], r[4]);
    P[4] = pk2(r[4], r[5]);
}

// Apply the per-pixel kernels (pixel-pair packed) to a loaded window.
__device__ __forceinline__ float4 apply_win(const float r[3][6], const u64 K2[9][2])
{
    u64 a0 = 0ull, a1 = 0ull;   // packed (0.f, 0.f)
    #pragma unroll
    for (int u = 0; u < 3; u++) {
        u64 P[5];
        make_pairs(r[u], P);
        #pragma unroll
        for (int v = 0; v < 3; v++) {
            const int c = u * 3 + v;
            a0 = ffma2(P[v],     K2[c][0], a0);   // pixels 0,1
            a1 = ffma2(P[v + 2], K2[c][1], a1);   // pixels 2,3
        }
    }
    float4 o;
    upk2(a0, o.x, o.y);
    upk2(a1, o.z, o.w);
    return o;
}

__global__ __launch_bounds__(128)
void fused_dynconv4x2(const float* __restrict__ image,
                      const float* __restrict__ x,
                      const float* __restrict__ Wt,
                      const float* __restrict__ bb,
                      float* __restrict__ y)
{
    // Duplicated weights: Wdup[t*10 + c] = (w, w), w = W[c][t].
    // Stride 10 float2 = 80B keeps each tap's row 16B-aligned -> LDS.128 pairs.
    __shared__ __align__(16) float2 Wdup[27 * 10];
    __shared__ __align__(8)  float2 bdup[9];

    const int tx  = threadIdx.x;          // 0..31
    const int ty  = threadIdx.y;          // 0..3
    const int tid = ty * 32 + tx;

    for (int idx = tid; idx < 243; idx += 128) {
        int c = idx / 27;
        int t = idx % 27;
        float w = Wt[idx];
        Wdup[t * 10 + c] = make_float2(w, w);
    }
    if (tid < 9) {
        float bv = bb[tid];
        bdup[tid] = make_float2(bv, bv);
    }
    __syncthreads();   // only barrier

    const int col0 = (blockIdx.x * 32 + tx) * 4;   // 4 px per thread, 16B aligned
    const int i    = blockIdx.y * 4 + ty;

    const bool rok0 = (i > 0);
    const bool rok2 = (i < HH - 1);
    const bool lok  = (col0 > 0);
    const bool rtok = (col0 < WW - 4);

    const float* xb = x + (size_t)i * WW + col0;
    float*       yb = y + (size_t)i * WW + col0;

    // ---- prefetch x[n=0]: the 9 LDGs fly during the whole K stage ----
    float A[3][6], B[3][6];
    load_win3(xb, rok0, rok2, lok, rtok, A);

    // ---------------- K stage: packed per-pixel 3x3 kernels ----------------
    u64 K2[9][2];   // K2[c][g]: g=0 -> pixels (0,1), g=1 -> pixels (2,3)
    #pragma unroll
    for (int c = 0; c < 9; c++) {
        u64 bp = *(const u64*)&bdup[c];
        K2[c][0] = bp;
        K2[c][1] = bp;
    }

    #pragma unroll
    for (int m = 0; m < 3; m++) {
        float r[3][6];
        const float* base = image + (size_t)(m * HH + i) * WW + col0;
        load_win3(base, rok0, rok2, lok, rtok, r);

        u64 P[3][5];
        make_pairs(r[0], P[0]);
        make_pairs(r[1], P[1]);
        make_pairs(r[2], P[2]);

        #pragma unroll
        for (int u = 0; u < 3; u++) {
            #pragma unroll
            for (int v = 0; v < 3; v++) {
                const int t = m * 9 + u * 3 + v;
                const u64* wd = (const u64*)&Wdup[t * 10];
                ulonglong2 w01 = *(const ulonglong2*)(wd + 0);   // (w0,w0),(w1,w1)
                ulonglong2 w23 = *(const ulonglong2*)(wd + 2);
                ulonglong2 w45 = *(const ulonglong2*)(wd + 4);
                ulonglong2 w67 = *(const ulonglong2*)(wd + 6);
                u64        w8  = wd[8];
                u64 wv[9] = {w01.x, w01.y, w23.x, w23.y,
                             w45.x, w45.y, w67.x, w67.y, w8};
                const u64 r0 = P[u][v];       // pixels (0,1)
                const u64 r1 = P[u][v + 2];   // pixels (2,3)
                #pragma unroll
                for (int c = 0; c < 9; c++) {
                    K2[c][0] = ffma2(wv[c], r0, K2[c][0]);
                    K2[c][1] = ffma2(wv[c], r1, K2[c][1]);
                }
            }
        }
    }

    // ------------- apply stage: double-buffered software pipeline -------------
    #pragma unroll
    for (int n = 0; n < NB; n += 2) {
        load_win3(xb + PLANE, rok0, rok2, lok, rtok, B);   // prefetch n+1

        *(float4*)yb = apply_win(A, K2);                   // compute/store n

        if (n + 2 < NB)
            load_win3(xb + 2 * PLANE, rok0, rok2, lok, rtok, A);  // prefetch n+2

        *(float4*)(yb + PLANE) = apply_win(B, K2);         // compute/store n+1

        xb += 2 * PLANE;
        yb += 2 * PLANE;
    }
}

extern "C" void kernel_launch(void* const* d_in, const int* in_sizes, int n_in,
                              void* d_out, int out_size)
{
    const float* image = (const float*)d_in[0];   // 3*512*512
    const float* x     = (const float*)d_in[1];   // 16*512*512
    const float* Wt    = (const float*)d_in[2];   // 243
    const float* bb    = (const float*)d_in[3];   // 9
    float* y = (float*)d_out;                     // 16*512*512

    dim3 block(32, 4);                 // 128 threads, each owns 4 horizontal pixels
    dim3 grid(WW / (32 * 4), HH / 4);  // (4, 128) = 512 blocks
    fused_dynconv4x2<<<grid, block>>>(image, x, Wt, bb, y);
}